// round 3
// baseline (speedup 1.0000x reference)
#include <cuda_runtime.h>

#define NDIM 2048
#define BKS 32                 // strips of 64 rows
#define NSTEPS 2112            // wavefront steps per strip
#define NGROUPS 264            // 8-step groups
#define NEGF (-1.4426950e10f)  // -1e10 in log2 domain
#define L2E 1.4426950408889634f
#define LN2 0.6931471805599453f
#define BLEN 2064              // boundary cols 0..2055, 16B aligned

// g_bnd[b][j] = V[64*(b+1), j] in log2 domain (col j at slot j)
__device__ __align__(16) float g_bnd[BKS][BLEN];
__device__ int g_prog[BKS * 32];   // [b*32] = # of 8-col chunks published by block b

__global__ void nw_init() {
    if (threadIdx.x < BKS) g_prog[threadIdx.x * 32] = 0;
}

__device__ __forceinline__ float ex2f_(float x) {
    float r; asm("ex2.approx.f32 %0, %1;" : "=f"(r) : "f"(x)); return r;
}
__device__ __forceinline__ float lg2f_(float x) {
    float r; asm("lg2.approx.f32 %0, %1;" : "=f"(r) : "f"(x)); return r;
}
__device__ __forceinline__ int ld_acq(const int* p) {
    int v; asm volatile("ld.acquire.gpu.global.b32 %0, [%1];" : "=r"(v) : "l"(p) : "memory");
    return v;
}

// Publish one aligned 8-col chunk + release counter. Predicated inside asm.
__device__ __forceinline__ void publish(float* dst, int* pp,
                                        float a0, float a1, float a2, float a3,
                                        float a4, float a5, float a6, float a7,
                                        int cnt, int flag) {
    asm volatile(
        "{\n\t"
        ".reg .pred p;\n\t"
        "setp.ne.s32 p, %11, 0;\n\t"
        "@p st.global.v4.f32 [%0], {%2, %3, %4, %5};\n\t"
        "@p st.global.v4.f32 [%0+16], {%6, %7, %8, %9};\n\t"
        "@p st.release.gpu.global.b32 [%1], %10;\n\t"
        "}"
        :: "l"(dst), "l"(pp),
           "f"(a0), "f"(a1), "f"(a2), "f"(a3),
           "f"(a4), "f"(a5), "f"(a6), "f"(a7),
           "r"(cnt), "r"(flag) : "memory");
}

// log2-domain smoothed max: th2 + Mx + log2(1 + 2^(mid-Mx) + 2^(lo-Mx))
__device__ __forceinline__ float lse2(float up, float dg, float lf,
                                      float A2, float th2) {
    float x  = up + A2;
    float y  = lf + A2;
    float w1 = fmaxf(dg, y);
    float w2 = fminf(dg, y);
    float Mx  = fmaxf(w1, x);
    float mid = fmaxf(fminf(x, w1), w2);
    float lo  = fminf(x, w2);
    float s = ex2f_(mid - Mx) + ex2f_(lo - Mx);
    return th2 + Mx + lg2f_(1.0f + s);
}

// 8 theta values (cols c..c+7, c even) via aligned float2, scaled to log2.
__device__ __forceinline__ void ldwin(const float* rp, int c, float* w) {
#pragma unroll
    for (int k = 0; k < 8; k += 2) {
        int cc = c + k;
        float2 v = make_float2(0.0f, 0.0f);
        if ((unsigned)cc < NDIM) v = *(const float2*)(rp + cc);
        w[k]   = v.x * L2E;
        w[k+1] = v.y * L2E;
    }
}

// 8 boundary floats (aligned window), L2-coherent (bypass L1)
__device__ __forceinline__ void load4(float* W, const float* p) {
    float4 a = __ldcg((const float4*)p);
    float4 c = __ldcg((const float4*)(p + 4));
    W[0]=a.x; W[1]=a.y; W[2]=a.z; W[3]=a.w;
    W[4]=c.x; W[5]=c.y; W[6]=c.z; W[7]=c.w;
}

__global__ void __launch_bounds__(32, 1)
nw_main(const float* __restrict__ theta, const float* __restrict__ Ap,
        float* __restrict__ out) {
    const int b = blockIdx.x;
    const int t = threadIdx.x;
    const float A2 = (*Ap) * L2E;
    const int R0 = b * 64;
    const bool iscons = (b > 0);

    // lane t owns rows R0+1+2t (cell0) and R0+2+2t (cell1)
    const float* th0p = theta + (size_t)(R0 + 2 * t) * NDIM;
    const float* th1p = th0p + NDIM;

    float v0m1 = NEGF, v0m2 = NEGF, v1m1 = NEGF;
    float sh_prev = NEGF;
    float bUprev = (b == 0) ? 0.0f : NEGF;   // V[R0, j0-1]; V[0,0]=0 for b==0

    float*       bout   = g_bnd[b];
    int*         myprog = &g_prog[b * 32];
    const float* bndp   = g_bnd[iscons ? b - 1 : 0];
    int*         progp  = &g_prog[(iscons ? b - 1 : 0) * 32];
    const int prodflag = (t == 31 && b < BKS - 1) ? 1 : 0;

    // theta windows (current + next), prefetched one group ahead
    const int c0base = -2 * t;
    float w0c[8], w1c[8], w0n[8], w1n[8];
    ldwin(th0p, c0base,     w0c);
    ldwin(th1p, c0base,     w1c);
    ldwin(th0p, c0base + 8, w0n);
    ldwin(th1p, c0base + 8, w1n);
    float th1carry = 0.0f;

    // boundary window ring: Wc = window g (cols 8g..8g+7), W1..W3 ahead
    float Wc[8], W1[8], W2[8], W3[8];
    int seen = 0;
    if (iscons) {
        // prologue slack: producer 15 groups ahead -> steady-state polls never spin
        while ((seen = ld_acq(progp)) < 8) { }
        load4(Wc, bndp + 0);
        load4(W1, bndp + 8);
        load4(W2, bndp + 16);
        load4(W3, bndp + 24);
    }

    float c6 = NEGF, c7 = NEGF;   // producer chunk carry (prev group's pb[6], pb[7])

    for (int g = 0; g < NGROUPS; ++g) {
        float pb[8];
#pragma unroll
        for (int q = 0; q < 8; ++q) {
            float bU = NEGF;
            if (iscons) bU = (q < 7) ? Wc[q + 1] : W1[0];   // col s+1
            float sh = __shfl_up_sync(0xffffffffu, v1m1, 1);
            float up0 = (t == 0) ? bU : sh;
            float dg0 = (t == 0) ? bUprev : sh_prev;
            float th0 = w0c[q];
            float th1 = (q == 0) ? th1carry : w1c[q - 1];

            float nv0 = lse2(up0, dg0, v0m1, A2, th0);
            float nv1 = lse2(v0m1, v0m2, v1m1, A2, th1);

            v0m2 = v0m1; v0m1 = nv0;
            sh_prev = sh; bUprev = bU;
            v1m1 = nv1;
            pb[q] = nv1;
        }

        // publish chunk m = g-8 (cols 8m..8m+7 <- steps 8m+62..8m+69)
        {
            const int flag = prodflag & (int)(g >= 8);
            publish(bout + 8 * (g - 8), myprog,
                    c6, c7, pb[0], pb[1], pb[2], pb[3], pb[4], pb[5],
                    g - 7, flag);
        }
        c6 = pb[6]; c7 = pb[7];

        // consumer: rotate ring, fetch window g+4 (poll is pipelined: `seen`
        // was loaded a full group ago; spin only during fill transients)
        if (iscons) {
#pragma unroll
            for (int k = 0; k < 8; ++k) { Wc[k] = W1[k]; W1[k] = W2[k]; W2[k] = W3[k]; }
            const int gd = g + 4;
            if (gd <= 256) {
                const int need = gd + 1;
                if (seen < need) {
                    do { seen = ld_acq(progp); } while (seen < need);
                }
                load4(W3, bndp + 8 * gd);
                seen = ld_acq(progp);   // pipelined refresh for next group's check
            }
        }

        // theta rotate + prefetch group g+2
        th1carry = w1c[7];
#pragma unroll
        for (int k = 0; k < 8; ++k) { w0c[k] = w0n[k]; w1c[k] = w1n[k]; }
        if (g + 2 < NGROUPS) {
            const int cpre = c0base + (g + 2) * 8;
            ldwin(th0p, cpre, w0n);
            ldwin(th1p, cpre, w1n);
        }
    }

    // epilogue: final chunk 256 (col 2048 = c6), counter past all needs
    publish(bout + 2048, myprog, c6, c7, c7, c7, c7, c7, c7, c7, 258, prodflag);

    // V[2048,2048] = lane31/block31 nv1 at step 2110 = c6
    if (b == BKS - 1 && t == 31) out[0] = c6 * LN2;
}

extern "C" void kernel_launch(void* const* d_in, const int* in_sizes, int n_in,
                              void* d_out, int out_size) {
    const float* theta = (const float*)d_in[0];
    const float* A     = (const float*)d_in[1];
    float* out         = (float*)d_out;
    nw_init<<<1, 32>>>();
    nw_main<<<BKS, 32>>>(theta, A, out);
}